// round 6
// baseline (speedup 1.0000x reference)
#include <cuda_runtime.h>
#include <math.h>

// Problem shape (fixed by the dataset): gen_img/target [8,20,1,512,512] f32,
// gen_D [8,1] f32. Output: 4 f32 scalars (L_total, L_rec, L_ssim, L_adv).
#define NFRAMES   160          // B*T
#define IMG_H     512
#define IMG_W     512
#define OUT_HW    506          // 512 - 6 (7x7 VALID)
#define STRIP_ROWS 128         // output rows per block strip
#define NSTRIPS   4            // ceil(506/128)
#define NWARPS    20           // ceil(506/26) warps cover 512 columns
#define NTHREADS  (NWARPS * 32)

// Global accumulators (device globals: no allocation allowed).
// [0] = sum |diff|, [1] = sum diff^2, [2] = sum SSIM(S)
__device__ double g_acc[3];

__global__ void gl_init_kernel() {
    g_acc[0] = 0.0; g_acc[1] = 0.0; g_acc[2] = 0.0;
}

// Windowed sum of 7 consecutive lanes: lane c gets v[c]+...+v[c+6].
// Valid for lanes 0..25. 4 shuffles via log-tree decomposition.
__device__ __forceinline__ float win7(float v) {
    const unsigned FULL = 0xffffffffu;
    float a = v + __shfl_down_sync(FULL, v, 1);   // a[c] = v[c]+v[c+1]
    float b = a + __shfl_down_sync(FULL, a, 2);   // b[c] = v[c..c+3]
    return b + __shfl_down_sync(FULL, a, 4)       // + v[c+4]+v[c+5]
             + __shfl_down_sync(FULL, v, 6);      // + v[c+6]
}

__global__ __launch_bounds__(NTHREADS)
void ssim_rec_kernel(const float* __restrict__ X, const float* __restrict__ Y) {
    const int strip = blockIdx.x;      // 0..3
    const int frame = blockIdx.y;      // 0..159
    const int lane  = threadIdx.x & 31;
    const int warp  = threadIdx.x >> 5;
    const int col   = warp * 26 + lane;        // input column (may exceed 511)
    const bool col_ok  = (col < IMG_W);
    const bool primary = (lane < 26) && col_ok;         // unique rec ownership of this column
    const bool out_ok  = (lane < 26) && (col <= OUT_HW - 1);  // produces SSIM output column

    const int r_start   = strip * STRIP_ROWS;                 // first input/output row
    const int out_r_end = min(r_start + STRIP_ROWS - 1, OUT_HW - 1);
    const int nrows     = (out_r_end + 6) - r_start + 1;      // input rows this strip

    const size_t fbase = (size_t)frame * (IMG_H * IMG_W);
    const int ccol = col_ok ? col : (IMG_W - 1);              // clamped address, value predicated
    const float* xr = X + fbase + (size_t)r_start * IMG_W + ccol;
    const float* yr = Y + fbase + (size_t)r_start * IMG_W + ccol;

    // ring buffers for the 7-row vertical window (static indices via unroll)
    float rx[7], ry[7];
#pragma unroll
    for (int i = 0; i < 7; ++i) { rx[i] = 0.0f; ry[i] = 0.0f; }

    float sx = 0.f, sy = 0.f, sxx = 0.f, syy = 0.f, sxy = 0.f;
    float a_abs = 0.f, a_sq = 0.f, a_S = 0.f;

    const float inv49 = 1.0f / 49.0f;
    const float C1 = 1e-4f;        // (0.01*255)^2 / 255^2
    const float C2 = 9e-4f;        // (0.03*255)^2 / 255^2
    const float cn  = 49.0f / 48.0f;   // sample-covariance correction
    const float cn2 = 2.0f * cn;

    for (int r0 = 0; r0 < nrows; r0 += 7) {
#pragma unroll
        for (int ph = 0; ph < 7; ++ph) {
            const int p = r0 + ph;                 // local input row index (uniform)
            if (p >= nrows) break;

            const size_t off = (size_t)p * IMG_W;
            float xv = col_ok ? __ldg(xr + off) : 0.0f;
            float yv = col_ok ? __ldg(yr + off) : 0.0f;

            // L_rec: each pixel counted exactly once (primary column, owned rows)
            if (primary && p < STRIP_ROWS) {
                float d = xv - yv;
                a_abs += fabsf(d);
                a_sq = fmaf(d, d, a_sq);
            }

            // vertical sliding window update
            const float ox = rx[ph], oy = ry[ph];
            sx += xv - ox;
            sy += yv - oy;
            sxx = fmaf(xv, xv, sxx); sxx = fmaf(-ox, ox, sxx);
            syy = fmaf(yv, yv, syy); syy = fmaf(-oy, oy, syy);
            sxy = fmaf(xv, yv, sxy); sxy = fmaf(-ox, oy, sxy);
            rx[ph] = xv; ry[ph] = yv;

            if (p >= 6) {   // vertical window full -> output row r_start + p - 6
                float hx  = win7(sx);
                float hy  = win7(sy);
                float hxx = win7(sxx);
                float hyy = win7(syy);
                float hxy = win7(sxy);

                float ux  = hx  * inv49;
                float uy  = hy  * inv49;
                float uxx = hxx * inv49;
                float uyy = hyy * inv49;
                float uxy = hxy * inv49;

                float Ax  = fmaf(-ux, ux, uxx);   // uxx - ux^2
                float Ay  = fmaf(-uy, uy, uyy);
                float Axy = fmaf(-ux, uy, uxy);

                float num1 = fmaf(2.0f * ux, uy, C1);
                float den1 = fmaf(ux, ux, fmaf(uy, uy, C1));
                float num2 = fmaf(cn2, Axy, C2);
                float den2 = fmaf(cn, Ax + Ay, C2);

                float S = __fdividef(num1 * num2, den1 * den2);
                if (out_ok) a_S += S;
            }
        }
    }

    // ---- block reduction ----
    const unsigned FULL = 0xffffffffu;
#pragma unroll
    for (int off = 16; off > 0; off >>= 1) {
        a_abs += __shfl_down_sync(FULL, a_abs, off);
        a_sq  += __shfl_down_sync(FULL, a_sq,  off);
        a_S   += __shfl_down_sync(FULL, a_S,   off);
    }

    __shared__ float s_abs[NWARPS], s_sq[NWARPS], s_S[NWARPS];
    if (lane == 0) { s_abs[warp] = a_abs; s_sq[warp] = a_sq; s_S[warp] = a_S; }
    __syncthreads();

    if (threadIdx.x == 0) {
        float t_abs = 0.f, t_sq = 0.f, t_S = 0.f;
#pragma unroll
        for (int i = 0; i < NWARPS; ++i) {
            t_abs += s_abs[i]; t_sq += s_sq[i]; t_S += s_S[i];
        }
        atomicAdd(&g_acc[0], (double)t_abs);
        atomicAdd(&g_acc[1], (double)t_sq);
        atomicAdd(&g_acc[2], (double)t_S);
    }
}

__global__ void gl_final_kernel(const float* __restrict__ genD, int nD,
                                float* __restrict__ out) {
    const double Ntot  = (double)NFRAMES * IMG_H * IMG_W;       // 41,943,040
    const double Nssim = (double)NFRAMES * OUT_HW * OUT_HW;     // 160*506*506

    double L_rec  = g_acc[0] / Ntot + g_acc[1] / Ntot;
    double L_ssim = g_acc[2] / Nssim;

    double s = 0.0;
    for (int i = 0; i < nD; ++i) s += (double)genD[i];
    double L_adv = -s / (double)nD;

    double L_total = L_rec + 0.01 * (1.0 - L_ssim) + 1e-4 * L_adv;

    out[0] = (float)L_total;
    out[1] = (float)L_rec;
    out[2] = (float)L_ssim;
    out[3] = (float)L_adv;
}

extern "C" void kernel_launch(void* const* d_in, const int* in_sizes, int n_in,
                              void* d_out, int out_size) {
    const float* gen_img = (const float*)d_in[0];
    const float* target  = (const float*)d_in[1];
    const float* gen_D   = (const float*)d_in[2];
    float* out = (float*)d_out;
    const int nD = in_sizes[2];

    gl_init_kernel<<<1, 1>>>();
    dim3 grid(NSTRIPS, NFRAMES);
    ssim_rec_kernel<<<grid, NTHREADS>>>(gen_img, target);
    gl_final_kernel<<<1, 1>>>(gen_D, nD, out);
}

// round 7
// speedup vs baseline: 1.8193x; 1.8193x over previous
#include <cuda_runtime.h>
#include <math.h>

// Shapes fixed by the dataset: gen_img/target [8,20,1,512,512] f32, gen_D [8,1].
#define NFRAMES   160
#define IMG_H     512
#define IMG_W     512
#define OUT_HW    506            // 512 - 6 (7x7 VALID)
#define NSTRIPS   8              // row strips of 64 output rows
#define NWARPS    9              // 9 warps x 58 output cols cover 506
#define NTHREADS  (NWARPS * 32)  // 288

// [0]=sum|d|, [1]=sum d^2, [2]=sum S
__device__ double g_acc[3];

__global__ void gl_init_kernel() {
    g_acc[0] = 0.0; g_acc[1] = 0.0; g_acc[2] = 0.0;
}

__global__ __launch_bounds__(NTHREADS, 3)
void ssim_rec_kernel(const float* __restrict__ X, const float* __restrict__ Y) {
    const int strip = blockIdx.x;       // 0..7
    const int frame = blockIdx.y;       // 0..159
    const int lane  = threadIdx.x & 31;
    const int warp  = threadIdx.x >> 5; // 0..8
    const unsigned FULL = 0xffffffffu;

    const int base = warp * 58;
    const int col  = base + 2 * lane;             // first of this thread's 2 cols
    const int ccol = min(col, IMG_W - 2);         // clamp (warp 8, lanes 24+)
    // rec ownership: unique column coverage (58 cols/warp; warp 8 owns up to 511)
    const bool own    = (warp < 8) ? (lane < 29) : (col < IMG_W);
    // SSIM output validity (2 output cols per lane, both valid together)
    const bool out_ok = (warp < 8) ? (lane <= 28) : (lane <= 20);

    const int r_start  = strip * 64;
    const int out_rows = (strip == 7) ? 58 : 64;
    const int nrows    = out_rows + 6;            // 70 or 64 input rows

    const size_t fbase = (size_t)frame * (IMG_H * IMG_W);
    const float2* xr = (const float2*)(X + fbase + (size_t)r_start * IMG_W) + (ccol >> 1);
    const float2* yr = (const float2*)(Y + fbase + (size_t)r_start * IMG_W) + (ccol >> 1);
    const int rstride = IMG_W / 2;                // float2 elements per row

    // vertical 7-row ring buffers (static indices via unroll-by-7 phases)
    float2 rx[7], ry[7];
#pragma unroll
    for (int i = 0; i < 7; ++i) {
        rx[i] = make_float2(0.f, 0.f);
        ry[i] = make_float2(0.f, 0.f);
    }
    // vertical running sums: x, y, x^2+y^2, xy (per column -> float2)
    float2 sx  = make_float2(0.f, 0.f), sy  = make_float2(0.f, 0.f);
    float2 s2  = make_float2(0.f, 0.f), sxy = make_float2(0.f, 0.f);

    float a_abs = 0.f, a_sq = 0.f, a_S = 0.f;

    // constants in window-sum space (x49^2): ratio-invariant rescale
    const float C1b = 1e-4f * 2401.0f;            // (0.01)^2 * 49^2
    const float C2b = 9e-4f * 2401.0f;            // (0.03)^2 * 49^2
    const float cn  = 49.0f / 48.0f;
    const float cn2 = 2.0f * cn;

#define PROC_ROW(SLOT, P, DO_OUT) do {                                          \
    const int _p = (P);                                                         \
    float2 xv = __ldg(xr + (size_t)_p * rstride);                               \
    float2 yv = __ldg(yr + (size_t)_p * rstride);                               \
    if (own && _p < 64) {                                                       \
        float d0 = xv.x - yv.x, d1 = xv.y - yv.y;                               \
        a_abs += fabsf(d0); a_abs += fabsf(d1);                                 \
        a_sq = fmaf(d0, d0, a_sq); a_sq = fmaf(d1, d1, a_sq);                   \
    }                                                                           \
    float2 ox = rx[SLOT], oy = ry[SLOT];                                        \
    sx.x += xv.x - ox.x;  sx.y += xv.y - ox.y;                                  \
    sy.x += yv.x - oy.x;  sy.y += yv.y - oy.y;                                  \
    s2.x += fmaf(xv.x, xv.x, yv.x * yv.x) - fmaf(ox.x, ox.x, oy.x * oy.x);      \
    s2.y += fmaf(xv.y, xv.y, yv.y * yv.y) - fmaf(ox.y, ox.y, oy.y * oy.y);      \
    sxy.x += fmaf(xv.x, yv.x, -(ox.x * oy.x));                                  \
    sxy.y += fmaf(xv.y, yv.y, -(ox.y * oy.y));                                  \
    rx[SLOT] = xv; ry[SLOT] = yv;                                               \
    if (DO_OUT) {                                                               \
        /* horizontal 7-window via pair sums: lane c owns cols 2c,2c+1 */       \
        float pX  = sx.x  + sx.y,  pY  = sy.x  + sy.y;                          \
        float p2  = s2.x  + s2.y,  pXY = sxy.x + sxy.y;                         \
        float pX1 = __shfl_down_sync(FULL, pX, 1);                              \
        float pX2 = __shfl_down_sync(FULL, pX, 2);                              \
        float pX3 = __shfl_down_sync(FULL, pX, 3);                              \
        float xX3 = __shfl_down_sync(FULL, sx.x, 3);                            \
        float pY1 = __shfl_down_sync(FULL, pY, 1);                              \
        float pY2 = __shfl_down_sync(FULL, pY, 2);                              \
        float pY3 = __shfl_down_sync(FULL, pY, 3);                              \
        float xY3 = __shfl_down_sync(FULL, sy.x, 3);                            \
        float p21 = __shfl_down_sync(FULL, p2, 1);                              \
        float p22 = __shfl_down_sync(FULL, p2, 2);                              \
        float p23 = __shfl_down_sync(FULL, p2, 3);                              \
        float x23 = __shfl_down_sync(FULL, s2.x, 3);                            \
        float pK1 = __shfl_down_sync(FULL, pXY, 1);                             \
        float pK2 = __shfl_down_sync(FULL, pXY, 2);                             \
        float pK3 = __shfl_down_sync(FULL, pXY, 3);                             \
        float xK3 = __shfl_down_sync(FULL, sxy.x, 3);                           \
        float cX = pX1 + pX2, cY = pY1 + pY2, c2 = p21 + p22, cK = pK1 + pK2;   \
        /* col 2c: p(c)+p(c+1)+p(c+2)+x(c+3); col 2c+1: y(c)+p(c+1)+p(c+2)+p(c+3) */ \
        float WX0 = pX + cX + xX3,   WX1 = sx.y  + cX + pX3;                    \
        float WY0 = pY + cY + xY3,   WY1 = sy.y  + cY + pY3;                    \
        float W20 = p2 + c2 + x23,   W21 = s2.y  + c2 + p23;                    \
        float WK0 = pXY + cK + xK3,  WK1 = sxy.y + cK + pK3;                    \
        /* SSIM in window-sum space (49^2 cancels in the ratio) */              \
        float t10 = WX0 * WY0;                                                  \
        float A10 = fmaf(t10, 2.0f, C1b);                                       \
        float m0  = WX0 * WX0;                                                  \
        float q0  = fmaf(WY0, WY0, m0);                                         \
        float B10 = q0 + C1b;                                                   \
        float t20 = fmaf(49.0f, WK0, -t10);                                     \
        float A20 = fmaf(cn2, t20, C2b);                                        \
        float u0  = fmaf(49.0f, W20, -q0);                                      \
        float B20 = fmaf(cn, u0, C2b);                                          \
        float S0  = __fdividef(A10 * A20, B10 * B20);                           \
        float t11 = WX1 * WY1;                                                  \
        float A11 = fmaf(t11, 2.0f, C1b);                                       \
        float m1  = WX1 * WX1;                                                  \
        float q1  = fmaf(WY1, WY1, m1);                                         \
        float B11 = q1 + C1b;                                                   \
        float t21 = fmaf(49.0f, WK1, -t11);                                     \
        float A21 = fmaf(cn2, t21, C2b);                                        \
        float u1  = fmaf(49.0f, W21, -q1);                                      \
        float B21 = fmaf(cn, u1, C2b);                                          \
        float S1  = __fdividef(A11 * A21, B11 * B21);                           \
        if (out_ok) { a_S += S0; a_S += S1; }                                   \
    }                                                                           \
} while (0)

    // prologue: 6 rows fill the vertical window, no outputs
    PROC_ROW(0, 0, false); PROC_ROW(1, 1, false); PROC_ROW(2, 2, false);
    PROC_ROW(3, 3, false); PROC_ROW(4, 4, false); PROC_ROW(5, 5, false);

    // main: rows p = 6..nrows-1, slot = p mod 7, unrolled by 7
    for (int pb = 6; pb < nrows; pb += 7) {
        PROC_ROW(6, pb, true);
        if (pb + 1 >= nrows) break;
        PROC_ROW(0, pb + 1, true);
        if (pb + 2 >= nrows) break;
        PROC_ROW(1, pb + 2, true);
        if (pb + 3 >= nrows) break;
        PROC_ROW(2, pb + 3, true);
        if (pb + 4 >= nrows) break;
        PROC_ROW(3, pb + 4, true);
        if (pb + 5 >= nrows) break;
        PROC_ROW(4, pb + 5, true);
        if (pb + 6 >= nrows) break;
        PROC_ROW(5, pb + 6, true);
    }
#undef PROC_ROW

    // ---- block reduction ----
#pragma unroll
    for (int off = 16; off > 0; off >>= 1) {
        a_abs += __shfl_down_sync(FULL, a_abs, off);
        a_sq  += __shfl_down_sync(FULL, a_sq,  off);
        a_S   += __shfl_down_sync(FULL, a_S,   off);
    }
    __shared__ float s_abs[NWARPS], s_sq[NWARPS], s_S[NWARPS];
    if (lane == 0) { s_abs[warp] = a_abs; s_sq[warp] = a_sq; s_S[warp] = a_S; }
    __syncthreads();
    if (threadIdx.x == 0) {
        float t_abs = 0.f, t_sq = 0.f, t_S = 0.f;
#pragma unroll
        for (int i = 0; i < NWARPS; ++i) {
            t_abs += s_abs[i]; t_sq += s_sq[i]; t_S += s_S[i];
        }
        atomicAdd(&g_acc[0], (double)t_abs);
        atomicAdd(&g_acc[1], (double)t_sq);
        atomicAdd(&g_acc[2], (double)t_S);
    }
}

__global__ void gl_final_kernel(const float* __restrict__ genD, int nD,
                                float* __restrict__ out) {
    const double Ntot  = (double)NFRAMES * IMG_H * IMG_W;
    const double Nssim = (double)NFRAMES * OUT_HW * OUT_HW;

    double L_rec  = g_acc[0] / Ntot + g_acc[1] / Ntot;
    double L_ssim = g_acc[2] / Nssim;

    double s = 0.0;
    for (int i = 0; i < nD; ++i) s += (double)genD[i];
    double L_adv = -s / (double)nD;

    double L_total = L_rec + 0.01 * (1.0 - L_ssim) + 1e-4 * L_adv;

    out[0] = (float)L_total;
    out[1] = (float)L_rec;
    out[2] = (float)L_ssim;
    out[3] = (float)L_adv;
}

extern "C" void kernel_launch(void* const* d_in, const int* in_sizes, int n_in,
                              void* d_out, int out_size) {
    const float* gen_img = (const float*)d_in[0];
    const float* target  = (const float*)d_in[1];
    const float* gen_D   = (const float*)d_in[2];
    float* out = (float*)d_out;
    const int nD = in_sizes[2];

    gl_init_kernel<<<1, 1>>>();
    dim3 grid(NSTRIPS, NFRAMES);
    ssim_rec_kernel<<<grid, NTHREADS>>>(gen_img, target);
    gl_final_kernel<<<1, 1>>>(gen_D, nD, out);
}